// round 5
// baseline (speedup 1.0000x reference)
#include <cuda_runtime.h>
#include <cuda_bf16.h>

// Problem constants
#define BATCH   2
#define AGENT   6
#define XW      8
#define YW      8
#define WIN     7
#define DIM     256
#define HEADS   8
#define DH      32
#define NWIN    (BATCH * XW * YW)      // 128 windows
#define NTOK    (AGENT * WIN * WIN)    // 294 tokens per window
#define MROWS   (NWIN * NTOK)          // 37632
#define NBIAS   1859                   // (2*6-1)*(13)*(13)

#define KPAD 36                        // K/V smem row pad (16B-aligned rows)
#define PROW_PAD 296                   // per-row P pad: 1184 B (16B aligned)
#define RPW 8                          // q-rows per warp
#define NGROUP 37                      // ceil(294/8)

__device__ int   g_rowbase[MROWS];
__device__ float g_qkv[(size_t)MROWS * 3 * DIM];   // ~115.6 MB
__device__ float g_att[(size_t)MROWS * DIM];       // ~38.5 MB

// ---------------------------------------------------------------------------
__global__ void rowbase_kernel(int* __restrict__ rb) {
    int m = blockIdx.x * 256 + threadIdx.x;
    if (m >= MROWS) return;
    int w = m / NTOK, t = m % NTOK;
    int b = w >> 6, xy = w & 63, x_ = xy >> 3, y_ = xy & 7;
    int l = t / 49, r = t % 49, w1 = r / 7, w2 = r % 7;
    rb[m] = ((((((b * AGENT + l) * XW + x_) * YW + y_) * WIN + w1) * WIN + w2)) * DIM;
}

// ---------------------------------------------------------------------------
// Tiled fp32 GEMM: C[m][n] = sum_k A[m][k] * W[n][k]   (K = 256 fixed)
// BM=BN=128, BK=16, 256 threads, 8x8 microtile in split 4+4 fragments
// (halves 64 apart -> 2-way max bank conflict), register prefetch.
// ---------------------------------------------------------------------------
template <int GATHER_A, int SCATTER_OUT>
__global__ void __launch_bounds__(256, 2)
gemm_kernel(const float* __restrict__ A, const int* __restrict__ rowbase,
            const float* __restrict__ W, float* __restrict__ C, int N) {
    __shared__ float As[16][132];
    __shared__ float Bs[16][132];

    int tid = threadIdx.x;
    int bm = blockIdx.y * 128;
    int bn = blockIdx.x * 128;

    int lr = tid >> 2;          // 0..63
    int lk = (tid & 3) * 4;     // 0,4,8,12

    long a0 = GATHER_A ? (long)rowbase[bm + lr]      : (long)(bm + lr) * DIM;
    long a1 = GATHER_A ? (long)rowbase[bm + lr + 64] : (long)(bm + lr + 64) * DIM;
    const float* ap0 = A + a0;
    const float* ap1 = A + a1;
    const float* bp0 = W + (long)(bn + lr) * DIM;
    const float* bp1 = W + (long)(bn + lr + 64) * DIM;

    int tx = tid & 15, ty = tid >> 4;
    float acc[8][8];
#pragma unroll
    for (int i = 0; i < 8; i++)
#pragma unroll
        for (int j = 0; j < 8; j++) acc[i][j] = 0.f;

    // prefetch first tile
    float4 av0 = *(const float4*)(ap0 + lk);
    float4 av1 = *(const float4*)(ap1 + lk);
    float4 bv0 = *(const float4*)(bp0 + lk);
    float4 bv1 = *(const float4*)(bp1 + lk);

    for (int k0 = 0; k0 < DIM; k0 += 16) {
        As[lk + 0][lr] = av0.x; As[lk + 1][lr] = av0.y;
        As[lk + 2][lr] = av0.z; As[lk + 3][lr] = av0.w;
        As[lk + 0][lr + 64] = av1.x; As[lk + 1][lr + 64] = av1.y;
        As[lk + 2][lr + 64] = av1.z; As[lk + 3][lr + 64] = av1.w;
        Bs[lk + 0][lr] = bv0.x; Bs[lk + 1][lr] = bv0.y;
        Bs[lk + 2][lr] = bv0.z; Bs[lk + 3][lr] = bv0.w;
        Bs[lk + 0][lr + 64] = bv1.x; Bs[lk + 1][lr + 64] = bv1.y;
        Bs[lk + 2][lr + 64] = bv1.z; Bs[lk + 3][lr + 64] = bv1.w;
        __syncthreads();

        if (k0 + 16 < DIM) {
            av0 = *(const float4*)(ap0 + k0 + 16 + lk);
            av1 = *(const float4*)(ap1 + k0 + 16 + lk);
            bv0 = *(const float4*)(bp0 + k0 + 16 + lk);
            bv1 = *(const float4*)(bp1 + k0 + 16 + lk);
        }

#pragma unroll
        for (int k = 0; k < 16; k++) {
            float4 aA = *(const float4*)&As[k][ty * 4];
            float4 aB = *(const float4*)&As[k][64 + ty * 4];
            float4 bA = *(const float4*)&Bs[k][tx * 4];
            float4 bB = *(const float4*)&Bs[k][64 + tx * 4];
            float ar[8] = {aA.x, aA.y, aA.z, aA.w, aB.x, aB.y, aB.z, aB.w};
            float br[8] = {bA.x, bA.y, bA.z, bA.w, bB.x, bB.y, bB.z, bB.w};
#pragma unroll
            for (int i = 0; i < 8; i++)
#pragma unroll
                for (int j = 0; j < 8; j++)
                    acc[i][j] = fmaf(ar[i], br[j], acc[i][j]);
        }
        __syncthreads();
    }

#pragma unroll
    for (int ih = 0; ih < 2; ih++) {
#pragma unroll
        for (int i = 0; i < 4; i++) {
            int mm = bm + ih * 64 + ty * 4 + i;
            float* cptr;
            if (SCATTER_OUT) cptr = C + (long)rowbase[mm];
            else             cptr = C + (long)mm * N;
            int ai = ih * 4 + i;
            int nn = bn + tx * 4;
            *(float4*)(cptr + nn)      = make_float4(acc[ai][0], acc[ai][1], acc[ai][2], acc[ai][3]);
            *(float4*)(cptr + nn + 64) = make_float4(acc[ai][4], acc[ai][5], acc[ai][6], acc[ai][7]);
        }
    }
}

// ---------------------------------------------------------------------------
// Attention: one block per (window, head). 256 threads = 8 warps.
// Each warp processes 8 query rows per group; K fragment held in registers
// across the 8 rows (jj-outer loop); raw scores go straight to smem P rows,
// softmax in place, then AV with 8 accumulators.
// ---------------------------------------------------------------------------
#define SM_K    0
#define SM_V    (NTOK * KPAD)                  // 10584
#define SM_Q    (SM_V + NTOK * KPAD)           // 21168
#define SM_BIAS (SM_Q + NTOK * DH)             // 30576
#define SM_MSK  (SM_BIAS + NBIAS)              // 32435
#define SM_CC   (SM_MSK + NTOK)                // 32729 (ints)
#define SM_P    33024                          // 16B aligned
#define SM_TOT  (SM_P + 64 * PROW_PAD)         // 51968 floats = 207,872 B

__global__ void __launch_bounds__(256)
attn_kernel(const float* __restrict__ qkv, const int* __restrict__ mask,
            const float* __restrict__ bias_table, float* __restrict__ aout) {
    extern __shared__ float sm[];
    float* Ks    = sm + SM_K;
    float* Vs    = sm + SM_V;
    float* Qs    = sm + SM_Q;
    float* biasC = sm + SM_BIAS;
    float* msk   = sm + SM_MSK;
    int*   ccode = (int*)(sm + SM_CC);
    float* prow  = sm + SM_P;

    const int w = blockIdx.x;
    const int h = blockIdx.y;
    const int tid = threadIdx.x;
    const float scale = 0.17677669529663687f;  // 32^-0.5

    // Stage Q, K, V for this (window, head)
    const float* qbase = qkv + (long)w * NTOK * (3 * DIM) + h * DH;
    for (int idx = tid; idx < NTOK * DH; idx += 256) {
        int t = idx >> 5, d = idx & 31;
        long o = (long)t * (3 * DIM) + d;
        Qs[t * DH + d]   = qbase[o];
        Ks[t * KPAD + d] = qbase[o + DIM];
        Vs[t * KPAD + d] = qbase[o + 2 * DIM];
    }
    for (int i = tid; i < NBIAS; i += 256) biasC[i] = bias_table[i * HEADS + h];
    const int* mbase = mask + (long)w * NTOK;
    for (int j = tid; j < NTOK; j += 256) {
        int l = j / 49, r = j % 49;
        msk[j] = (float)mbase[r * AGENT + l];
        int w1 = r / 7, w2 = r % 7;
        ccode[j] = l * 169 + w1 * 13 + w2;
    }
    __syncthreads();

    const int warp = tid >> 5, lane = tid & 31;
    float* pbase = prow + warp * RPW * PROW_PAD;

    for (int g = warp; g < NGROUP; g += 8) {
        const int i0 = g * RPW;
        const int nrows = (NTOK - i0 < RPW) ? (NTOK - i0) : RPW;

        int rc[RPW];
#pragma unroll
        for (int r = 0; r < RPW; r++) {
            int ir = i0 + r; if (ir >= NTOK) ir = NTOK - 1;
            rc[r] = ccode[ir] + 929;          // 5*169 + 6*13 + 6
        }

        // QK^T: jj outer so the K fragment (32 regs) is reused for 8 rows
#pragma unroll
        for (int jj = 0; jj < 10; jj++) {
            int j = lane + jj * 32;
            bool jv = (j < NTOK);
            int jc = jv ? j : 0;
            const float4* k4 = (const float4*)(Ks + jc * KPAD);
            float4 kr[8];
#pragma unroll
            for (int d = 0; d < 8; d++) kr[d] = k4[d];
            int   ccj = ccode[jc];
            float mj  = msk[jc];
#pragma unroll
            for (int r = 0; r < RPW; r++) {
                int ir = i0 + r; if (ir >= NTOK) ir = NTOK - 1;
                const float4* q4 = (const float4*)(Qs + ir * DH);
                float acc = 0.f;
#pragma unroll
                for (int d = 0; d < 8; d++) {
                    float4 a = q4[d], c = kr[d];
                    acc = fmaf(a.x, c.x, acc);
                    acc = fmaf(a.y, c.y, acc);
                    acc = fmaf(a.z, c.z, acc);
                    acc = fmaf(a.w, c.w, acc);
                }
                float sv = fmaf(acc, scale, biasC[rc[r] - ccj]);
                sv = (mj == 0.f) ? -1e9f : sv;     // replace semantics (jnp.where)
                if (jv) pbase[r * PROW_PAD + j] = sv;
            }
        }
        __syncwarp();

        // Softmax per row, in place
#pragma unroll
        for (int r = 0; r < RPW; r++) {
            float* prw = pbase + r * PROW_PAD;
            float e[10];
            float mx = -3.0e38f;
#pragma unroll
            for (int t = 0; t < 10; t++) {
                int j = lane + t * 32;
                e[t] = (j < NTOK) ? prw[j] : -3.0e38f;
                mx = fmaxf(mx, e[t]);
            }
#pragma unroll
            for (int o = 16; o > 0; o >>= 1) mx = fmaxf(mx, __shfl_xor_sync(0xffffffffu, mx, o));
            float sum = 0.f;
#pragma unroll
            for (int t = 0; t < 10; t++) {
                e[t] = __expf(e[t] - mx);
                sum += e[t];
            }
#pragma unroll
            for (int o = 16; o > 0; o >>= 1) sum += __shfl_xor_sync(0xffffffffu, sum, o);
            float inv = 1.f / sum;
#pragma unroll
            for (int t = 0; t < 10; t++) {
                int j = lane + t * 32;
                if (j < NTOK) prw[j] = e[t] * inv;
            }
            if (lane < 2) prw[NTOK + lane] = 0.f;   // zero pad for float4 AV loop
        }
        __syncwarp();

        // AV: o[r][lane] = sum_j p_r[j] * V[j][lane]; V loaded once per 8 rows
        float o[RPW];
#pragma unroll
        for (int r = 0; r < RPW; r++) o[r] = 0.f;
#pragma unroll 2
        for (int j = 0; j < NTOK; j += 4) {
            float v0 = Vs[(j + 0) * KPAD + lane];
            float v1 = Vs[(j + 1) * KPAD + lane];
            float v2 = Vs[(j + 2) * KPAD + lane];
            float v3 = Vs[(j + 3) * KPAD + lane];
#pragma unroll
            for (int r = 0; r < RPW; r++) {
                float4 p = *(const float4*)(pbase + r * PROW_PAD + j);
                o[r] = fmaf(p.x, v0, o[r]);
                o[r] = fmaf(p.y, v1, o[r]);
                o[r] = fmaf(p.z, v2, o[r]);
                o[r] = fmaf(p.w, v3, o[r]);
            }
        }
        // j=292 chunk reads p[294..295]=0; V rows 294/295 hold staged Q floats
        // (finite), multiplied by exactly 0 -> no contribution.

#pragma unroll
        for (int r = 0; r < RPW; r++) {
            if (r < nrows)
                aout[((long)w * NTOK + (i0 + r)) * DIM + h * DH + lane] = o[r];
        }
        __syncwarp();
    }
}

// ---------------------------------------------------------------------------
extern "C" void kernel_launch(void* const* d_in, const int* in_sizes, int n_in,
                              void* d_out, int out_size) {
    const float* x          = (const float*)d_in[0];
    const int*   mask       = (const int*)d_in[1];
    const float* w_qkv      = (const float*)d_in[2];
    const float* w_out      = (const float*)d_in[3];
    const float* bias_table = (const float*)d_in[4];
    float* out = (float*)d_out;

    void *rbp_, *qkvp_, *attp_;
    cudaGetSymbolAddress(&rbp_, g_rowbase);
    cudaGetSymbolAddress(&qkvp_, g_qkv);
    cudaGetSymbolAddress(&attp_, g_att);
    int*   rb   = (int*)rbp_;
    float* qkvb = (float*)qkvp_;
    float* attb = (float*)attp_;

    cudaFuncSetAttribute(attn_kernel, cudaFuncAttributeMaxDynamicSharedMemorySize,
                         SM_TOT * (int)sizeof(float));

    rowbase_kernel<<<(MROWS + 255) / 256, 256>>>(rb);

    // QKV projection: (37632 x 256) @ (768 x 256)^T -> (37632 x 768)
    {
        dim3 grid(3 * DIM / 128, MROWS / 128);
        gemm_kernel<1, 0><<<grid, 256>>>(x, rb, w_qkv, qkvb, 3 * DIM);
    }

    // Attention per (window, head)
    {
        dim3 grid(NWIN, HEADS);
        attn_kernel<<<grid, 256, SM_TOT * (int)sizeof(float)>>>(qkvb, mask, bias_table, attb);
    }

    // Output projection + scatter to (B, L, X, Y, W1, W2, C)
    {
        dim3 grid(DIM / 128, MROWS / 128);
        gemm_kernel<0, 1><<<grid, 256>>>(attb, rb, w_out, out, DIM);
    }
}

// round 7
// speedup vs baseline: 1.2499x; 1.2499x over previous
#include <cuda_runtime.h>
#include <cuda_bf16.h>

// Problem constants
#define BATCH   2
#define AGENT   6
#define XW      8
#define YW      8
#define WIN     7
#define DIM     256
#define HEADS   8
#define DH      32
#define NWIN    (BATCH * XW * YW)      // 128 windows
#define NTOK    (AGENT * WIN * WIN)    // 294 tokens per window
#define MROWS   (NWIN * NTOK)          // 37632
#define NBIAS   1859                   // (2*6-1)*(13)*(13)

#define KPAD 36                        // K/V smem row pad (16B-aligned rows)
#define PROW_PAD 296                   // per-row P pad: 1184 B (16B aligned)
#define NGROUP 74                      // ceil(294/4) row groups

__device__ int   g_rowbase[MROWS];
__device__ float g_qkv[(size_t)MROWS * 3 * DIM];   // ~115.6 MB
__device__ float g_att[(size_t)MROWS * DIM];       // ~38.5 MB

// ---------------------------------------------------------------------------
__global__ void rowbase_kernel(int* __restrict__ rb) {
    int m = blockIdx.x * 256 + threadIdx.x;
    if (m >= MROWS) return;
    int w = m / NTOK, t = m % NTOK;
    int b = w >> 6, xy = w & 63, x_ = xy >> 3, y_ = xy & 7;
    int l = t / 49, r = t % 49, w1 = r / 7, w2 = r % 7;
    rb[m] = ((((((b * AGENT + l) * XW + x_) * YW + y_) * WIN + w1) * WIN + w2)) * DIM;
}

// ---------------------------------------------------------------------------
// Tiled fp32 GEMM (R5 version — measured win): BM=BN=128, BK=16, 256 threads,
// 8x8 microtile in split 4+4 fragments (2-way max conflict), reg prefetch.
// ---------------------------------------------------------------------------
template <int GATHER_A, int SCATTER_OUT>
__global__ void __launch_bounds__(256, 2)
gemm_kernel(const float* __restrict__ A, const int* __restrict__ rowbase,
            const float* __restrict__ W, float* __restrict__ C, int N) {
    __shared__ float As[16][132];
    __shared__ float Bs[16][132];

    int tid = threadIdx.x;
    int bm = blockIdx.y * 128;
    int bn = blockIdx.x * 128;

    int lr = tid >> 2;          // 0..63
    int lk = (tid & 3) * 4;     // 0,4,8,12

    long a0 = GATHER_A ? (long)rowbase[bm + lr]      : (long)(bm + lr) * DIM;
    long a1 = GATHER_A ? (long)rowbase[bm + lr + 64] : (long)(bm + lr + 64) * DIM;
    const float* ap0 = A + a0;
    const float* ap1 = A + a1;
    const float* bp0 = W + (long)(bn + lr) * DIM;
    const float* bp1 = W + (long)(bn + lr + 64) * DIM;

    int tx = tid & 15, ty = tid >> 4;
    float acc[8][8];
#pragma unroll
    for (int i = 0; i < 8; i++)
#pragma unroll
        for (int j = 0; j < 8; j++) acc[i][j] = 0.f;

    // prefetch first tile
    float4 av0 = *(const float4*)(ap0 + lk);
    float4 av1 = *(const float4*)(ap1 + lk);
    float4 bv0 = *(const float4*)(bp0 + lk);
    float4 bv1 = *(const float4*)(bp1 + lk);

    for (int k0 = 0; k0 < DIM; k0 += 16) {
        As[lk + 0][lr] = av0.x; As[lk + 1][lr] = av0.y;
        As[lk + 2][lr] = av0.z; As[lk + 3][lr] = av0.w;
        As[lk + 0][lr + 64] = av1.x; As[lk + 1][lr + 64] = av1.y;
        As[lk + 2][lr + 64] = av1.z; As[lk + 3][lr + 64] = av1.w;
        Bs[lk + 0][lr] = bv0.x; Bs[lk + 1][lr] = bv0.y;
        Bs[lk + 2][lr] = bv0.z; Bs[lk + 3][lr] = bv0.w;
        Bs[lk + 0][lr + 64] = bv1.x; Bs[lk + 1][lr + 64] = bv1.y;
        Bs[lk + 2][lr + 64] = bv1.z; Bs[lk + 3][lr + 64] = bv1.w;
        __syncthreads();

        if (k0 + 16 < DIM) {
            av0 = *(const float4*)(ap0 + k0 + 16 + lk);
            av1 = *(const float4*)(ap1 + k0 + 16 + lk);
            bv0 = *(const float4*)(bp0 + k0 + 16 + lk);
            bv1 = *(const float4*)(bp1 + k0 + 16 + lk);
        }

#pragma unroll
        for (int k = 0; k < 16; k++) {
            float4 aA = *(const float4*)&As[k][ty * 4];
            float4 aB = *(const float4*)&As[k][64 + ty * 4];
            float4 bA = *(const float4*)&Bs[k][tx * 4];
            float4 bB = *(const float4*)&Bs[k][64 + tx * 4];
            float ar[8] = {aA.x, aA.y, aA.z, aA.w, aB.x, aB.y, aB.z, aB.w};
            float br[8] = {bA.x, bA.y, bA.z, bA.w, bB.x, bB.y, bB.z, bB.w};
#pragma unroll
            for (int i = 0; i < 8; i++)
#pragma unroll
                for (int j = 0; j < 8; j++)
                    acc[i][j] = fmaf(ar[i], br[j], acc[i][j]);
        }
        __syncthreads();
    }

#pragma unroll
    for (int ih = 0; ih < 2; ih++) {
#pragma unroll
        for (int i = 0; i < 4; i++) {
            int mm = bm + ih * 64 + ty * 4 + i;
            float* cptr;
            if (SCATTER_OUT) cptr = C + (long)rowbase[mm];
            else             cptr = C + (long)mm * N;
            int ai = ih * 4 + i;
            int nn = bn + tx * 4;
            *(float4*)(cptr + nn)      = make_float4(acc[ai][0], acc[ai][1], acc[ai][2], acc[ai][3]);
            *(float4*)(cptr + nn + 64) = make_float4(acc[ai][4], acc[ai][5], acc[ai][6], acc[ai][7]);
        }
    }
}

// ---------------------------------------------------------------------------
// Attention (R3 version — measured good): one block per (window, head),
// 512 threads = 16 warps, 4 query rows per warp per group.
// ---------------------------------------------------------------------------
#define SM_K    0
#define SM_V    (NTOK * KPAD)                  // 10584
#define SM_Q    (SM_V + NTOK * KPAD)           // 21168
#define SM_BIAS (SM_Q + NTOK * DH)             // 30576
#define SM_MSK  (SM_BIAS + NBIAS)              // 32435
#define SM_CC   (SM_MSK + NTOK)                // 32729 (ints)
#define SM_P    33024                          // 16B aligned
#define SM_TOT  (SM_P + 64 * PROW_PAD)         // 51968 floats = 207,872 B

__global__ void __launch_bounds__(512)
attn_kernel(const float* __restrict__ qkv, const int* __restrict__ mask,
            const float* __restrict__ bias_table, float* __restrict__ aout) {
    extern __shared__ float sm[];
    float* Ks    = sm + SM_K;
    float* Vs    = sm + SM_V;
    float* Qs    = sm + SM_Q;
    float* biasC = sm + SM_BIAS;
    float* msk   = sm + SM_MSK;
    int*   ccode = (int*)(sm + SM_CC);
    float* prow  = sm + SM_P;

    const int w = blockIdx.x;
    const int h = blockIdx.y;
    const int tid = threadIdx.x;
    const float scale = 0.17677669529663687f;  // 32^-0.5

    // Stage Q, K, V for this (window, head)
    const float* qbase = qkv + (long)w * NTOK * (3 * DIM) + h * DH;
    for (int idx = tid; idx < NTOK * DH; idx += 512) {
        int t = idx >> 5, d = idx & 31;
        long o = (long)t * (3 * DIM) + d;
        Qs[t * DH + d]   = qbase[o];
        Ks[t * KPAD + d] = qbase[o + DIM];
        Vs[t * KPAD + d] = qbase[o + 2 * DIM];
    }
    for (int i = tid; i < NBIAS; i += 512) biasC[i] = bias_table[i * HEADS + h];
    const int* mbase = mask + (long)w * NTOK;
    for (int j = tid; j < NTOK; j += 512) {
        int l = j / 49, r = j % 49;
        msk[j] = (float)mbase[r * AGENT + l];
        int w1 = r / 7, w2 = r % 7;
        ccode[j] = l * 169 + w1 * 13 + w2;
    }
    __syncthreads();

    const int warp = tid >> 5, lane = tid & 31;

    for (int g = warp; g < NGROUP; g += 16) {
        const int i0 = g * 4;
        const int nrows = (NTOK - i0 < 4) ? (NTOK - i0) : 4;

        int rc[4];
#pragma unroll
        for (int r = 0; r < 4; r++) {
            int ir = i0 + r; if (ir >= NTOK) ir = NTOK - 1;
            rc[r] = ccode[ir] + 929;          // 5*169 + 6*13 + 6
        }

        float s[4][10];
#pragma unroll
        for (int jj = 0; jj < 10; jj++) {
            int j = lane + jj * 32;
            bool jv = (j < NTOK);
            int jc = jv ? j : 0;
            const float4* k4 = (const float4*)(Ks + jc * KPAD);
            float4 kr[8];
#pragma unroll
            for (int d = 0; d < 8; d++) kr[d] = k4[d];
            int   ccj = ccode[jc];
            float mj  = msk[jc];
#pragma unroll
            for (int r = 0; r < 4; r++) {
                int ir = i0 + r; if (ir >= NTOK) ir = NTOK - 1;
                const float4* q4 = (const float4*)(Qs + ir * DH);
                float acc = 0.f;
#pragma unroll
                for (int d = 0; d < 8; d++) {
                    float4 a = q4[d], c = kr[d];
                    acc = fmaf(a.x, c.x, acc);
                    acc = fmaf(a.y, c.y, acc);
                    acc = fmaf(a.z, c.z, acc);
                    acc = fmaf(a.w, c.w, acc);
                }
                float sv = fmaf(acc, scale, biasC[rc[r] - ccj]);
                sv = (mj == 0.f) ? -1e9f : sv;     // replace semantics (jnp.where)
                s[r][jj] = jv ? sv : -3.0e38f;
            }
        }

        // Softmax per row; write normalized P rows to smem
#pragma unroll
        for (int r = 0; r < 4; r++) {
            float mx = s[r][0];
#pragma unroll
            for (int jj = 1; jj < 10; jj++) mx = fmaxf(mx, s[r][jj]);
#pragma unroll
            for (int o = 16; o > 0; o >>= 1) mx = fmaxf(mx, __shfl_xor_sync(0xffffffffu, mx, o));
            float sum = 0.f;
#pragma unroll
            for (int jj = 0; jj < 10; jj++) {
                float e = __expf(s[r][jj] - mx);
                s[r][jj] = e;
                sum += e;
            }
#pragma unroll
            for (int o = 16; o > 0; o >>= 1) sum += __shfl_xor_sync(0xffffffffu, sum, o);
            float inv = 1.f / sum;
            float* prw = prow + (warp * 4 + r) * PROW_PAD;
#pragma unroll
            for (int jj = 0; jj < 10; jj++) {
                int j = lane + jj * 32;
                if (j < NTOK) prw[j] = s[r][jj] * inv;
            }
            if (lane < 2) prw[NTOK + lane] = 0.f;   // zero pad for float4 AV loop
        }
        __syncwarp();

        // AV: o[r][lane] = sum_j p_r[j] * V[j][lane]; V loaded once per 4 rows
        const float* p0 = prow + (warp * 4 + 0) * PROW_PAD;
        const float* p1 = prow + (warp * 4 + 1) * PROW_PAD;
        const float* p2 = prow + (warp * 4 + 2) * PROW_PAD;
        const float* p3 = prow + (warp * 4 + 3) * PROW_PAD;
        float o0 = 0.f, o1 = 0.f, o2 = 0.f, o3 = 0.f;
#pragma unroll 2
        for (int j = 0; j < NTOK; j += 4) {
            float4 a = *(const float4*)(p0 + j);
            float4 b = *(const float4*)(p1 + j);
            float4 c = *(const float4*)(p2 + j);
            float4 d = *(const float4*)(p3 + j);
            float v0 = Vs[(j + 0) * KPAD + lane];
            float v1 = Vs[(j + 1) * KPAD + lane];
            float v2 = Vs[(j + 2) * KPAD + lane];
            float v3 = Vs[(j + 3) * KPAD + lane];
            o0 = fmaf(a.x, v0, o0); o0 = fmaf(a.y, v1, o0); o0 = fmaf(a.z, v2, o0); o0 = fmaf(a.w, v3, o0);
            o1 = fmaf(b.x, v0, o1); o1 = fmaf(b.y, v1, o1); o1 = fmaf(b.z, v2, o1); o1 = fmaf(b.w, v3, o1);
            o2 = fmaf(c.x, v0, o2); o2 = fmaf(c.y, v1, o2); o2 = fmaf(c.z, v2, o2); o2 = fmaf(c.w, v3, o2);
            o3 = fmaf(d.x, v0, o3); o3 = fmaf(d.y, v1, o3); o3 = fmaf(d.z, v2, o3); o3 = fmaf(d.w, v3, o3);
        }
        // j=292 chunk reads p[294..295]=0; V rows 294/295 hold staged Q floats
        // (finite), multiplied by exactly 0 -> no contribution.

        float ov[4] = {o0, o1, o2, o3};
#pragma unroll
        for (int r = 0; r < 4; r++) {
            if (r < nrows)
                aout[((long)w * NTOK + (i0 + r)) * DIM + h * DH + lane] = ov[r];
        }
        __syncwarp();
    }
}

// ---------------------------------------------------------------------------
extern "C" void kernel_launch(void* const* d_in, const int* in_sizes, int n_in,
                              void* d_out, int out_size) {
    const float* x          = (const float*)d_in[0];
    const int*   mask       = (const int*)d_in[1];
    const float* w_qkv      = (const float*)d_in[2];
    const float* w_out      = (const float*)d_in[3];
    const float* bias_table = (const float*)d_in[4];
    float* out = (float*)d_out;

    void *rbp_, *qkvp_, *attp_;
    cudaGetSymbolAddress(&rbp_, g_rowbase);
    cudaGetSymbolAddress(&qkvp_, g_qkv);
    cudaGetSymbolAddress(&attp_, g_att);
    int*   rb   = (int*)rbp_;
    float* qkvb = (float*)qkvp_;
    float* attb = (float*)attp_;

    cudaFuncSetAttribute(attn_kernel, cudaFuncAttributeMaxDynamicSharedMemorySize,
                         SM_TOT * (int)sizeof(float));

    rowbase_kernel<<<(MROWS + 255) / 256, 256>>>(rb);

    // QKV projection: (37632 x 256) @ (768 x 256)^T -> (37632 x 768)
    {
        dim3 grid(3 * DIM / 128, MROWS / 128);
        gemm_kernel<1, 0><<<grid, 256>>>(x, rb, w_qkv, qkvb, 3 * DIM);
    }

    // Attention per (window, head)
    {
        dim3 grid(NWIN, HEADS);
        attn_kernel<<<grid, 512, SM_TOT * (int)sizeof(float)>>>(qkvb, mask, bias_table, attb);
    }

    // Output projection + scatter to (B, L, X, Y, W1, W2, C)
    {
        dim3 grid(DIM / 128, MROWS / 128);
        gemm_kernel<0, 1><<<grid, 256>>>(attb, rb, w_out, out, DIM);
    }
}

// round 13
// speedup vs baseline: 2.0526x; 1.6423x over previous
#include <cuda_runtime.h>
#include <cuda_fp16.h>
#include <cuda_bf16.h>
#include <cstdint>
#include <cstring>

typedef unsigned int u32;

// Problem constants
#define BATCH   2
#define AGENT   6
#define XW      8
#define YW      8
#define WIN     7
#define DIM     256
#define HEADS   8
#define DH      32
#define NWIN    (BATCH * XW * YW)      // 128 windows
#define NTOK    (AGENT * WIN * WIN)    // 294 tokens per window
#define MROWS   (NWIN * NTOK)          // 37632
#define NBIAS   1859                   // (2*6-1)*13*13

#define NPAD    304                    // NTOK padded to 19*16
#define QKPAD   40                     // halves per row (80 B: conflict-free ldmatrix)

__device__ int   g_rowbase[MROWS];
__device__ float g_qkv[(size_t)MROWS * 3 * DIM];   // ~115.6 MB
__device__ float g_att[(size_t)MROWS * DIM];       // ~38.5 MB

// ---------------------------------------------------------------------------
__global__ void rowbase_kernel(int* __restrict__ rb) {
    int m = blockIdx.x * 256 + threadIdx.x;
    if (m >= MROWS) return;
    int w = m / NTOK, t = m % NTOK;
    int b = w >> 6, xy = w & 63, x_ = xy >> 3, y_ = xy & 7;
    int l = t / 49, r = t % 49, w1 = r / 7, w2 = r % 7;
    rb[m] = ((((((b * AGENT + l) * XW + x_) * YW + y_) * WIN + w1) * WIN + w2)) * DIM;
}

// ---------------------------------------------------------------------------
// Tiled fp32 GEMM (R5/R7 version — measured win): BM=BN=128, BK=16, 256 thr,
// 8x8 microtile in split 4+4 fragments, register prefetch.
// ---------------------------------------------------------------------------
template <int GATHER_A, int SCATTER_OUT>
__global__ void __launch_bounds__(256, 2)
gemm_kernel(const float* __restrict__ A, const int* __restrict__ rowbase,
            const float* __restrict__ W, float* __restrict__ C, int N) {
    __shared__ float As[16][132];
    __shared__ float Bs[16][132];

    int tid = threadIdx.x;
    int bm = blockIdx.y * 128;
    int bn = blockIdx.x * 128;

    int lr = tid >> 2;
    int lk = (tid & 3) * 4;

    long a0 = GATHER_A ? (long)rowbase[bm + lr]      : (long)(bm + lr) * DIM;
    long a1 = GATHER_A ? (long)rowbase[bm + lr + 64] : (long)(bm + lr + 64) * DIM;
    const float* ap0 = A + a0;
    const float* ap1 = A + a1;
    const float* bp0 = W + (long)(bn + lr) * DIM;
    const float* bp1 = W + (long)(bn + lr + 64) * DIM;

    int tx = tid & 15, ty = tid >> 4;
    float acc[8][8];
#pragma unroll
    for (int i = 0; i < 8; i++)
#pragma unroll
        for (int j = 0; j < 8; j++) acc[i][j] = 0.f;

    float4 av0 = *(const float4*)(ap0 + lk);
    float4 av1 = *(const float4*)(ap1 + lk);
    float4 bv0 = *(const float4*)(bp0 + lk);
    float4 bv1 = *(const float4*)(bp1 + lk);

    for (int k0 = 0; k0 < DIM; k0 += 16) {
        As[lk + 0][lr] = av0.x; As[lk + 1][lr] = av0.y;
        As[lk + 2][lr] = av0.z; As[lk + 3][lr] = av0.w;
        As[lk + 0][lr + 64] = av1.x; As[lk + 1][lr + 64] = av1.y;
        As[lk + 2][lr + 64] = av1.z; As[lk + 3][lr + 64] = av1.w;
        Bs[lk + 0][lr] = bv0.x; Bs[lk + 1][lr] = bv0.y;
        Bs[lk + 2][lr] = bv0.z; Bs[lk + 3][lr] = bv0.w;
        Bs[lk + 0][lr + 64] = bv1.x; Bs[lk + 1][lr + 64] = bv1.y;
        Bs[lk + 2][lr + 64] = bv1.z; Bs[lk + 3][lr + 64] = bv1.w;
        __syncthreads();

        if (k0 + 16 < DIM) {
            av0 = *(const float4*)(ap0 + k0 + 16 + lk);
            av1 = *(const float4*)(ap1 + k0 + 16 + lk);
            bv0 = *(const float4*)(bp0 + k0 + 16 + lk);
            bv1 = *(const float4*)(bp1 + k0 + 16 + lk);
        }

#pragma unroll
        for (int k = 0; k < 16; k++) {
            float4 aA = *(const float4*)&As[k][ty * 4];
            float4 aB = *(const float4*)&As[k][64 + ty * 4];
            float4 bA = *(const float4*)&Bs[k][tx * 4];
            float4 bB = *(const float4*)&Bs[k][64 + tx * 4];
            float ar[8] = {aA.x, aA.y, aA.z, aA.w, aB.x, aB.y, aB.z, aB.w};
            float br[8] = {bA.x, bA.y, bA.z, bA.w, bB.x, bB.y, bB.z, bB.w};
#pragma unroll
            for (int i = 0; i < 8; i++)
#pragma unroll
                for (int j = 0; j < 8; j++)
                    acc[i][j] = fmaf(ar[i], br[j], acc[i][j]);
        }
        __syncthreads();
    }

#pragma unroll
    for (int ih = 0; ih < 2; ih++) {
#pragma unroll
        for (int i = 0; i < 4; i++) {
            int mm = bm + ih * 64 + ty * 4 + i;
            float* cptr;
            if (SCATTER_OUT) cptr = C + (long)rowbase[mm];
            else             cptr = C + (long)mm * N;
            int ai = ih * 4 + i;
            int nn = bn + tx * 4;
            *(float4*)(cptr + nn)      = make_float4(acc[ai][0], acc[ai][1], acc[ai][2], acc[ai][3]);
            *(float4*)(cptr + nn + 64) = make_float4(acc[ai][4], acc[ai][5], acc[ai][6], acc[ai][7]);
        }
    }
}

// ---------------------------------------------------------------------------
// mma.sync helpers
// ---------------------------------------------------------------------------
__device__ __forceinline__ void ldsm4(u32* r, const __half* p) {
    u32 a = (u32)__cvta_generic_to_shared(p);
    asm volatile("ldmatrix.sync.aligned.m8n8.x4.shared.b16 {%0,%1,%2,%3}, [%4];"
                 : "=r"(r[0]), "=r"(r[1]), "=r"(r[2]), "=r"(r[3]) : "r"(a));
}
__device__ __forceinline__ void ldsm4t(u32* r, const __half* p) {
    u32 a = (u32)__cvta_generic_to_shared(p);
    asm volatile("ldmatrix.sync.aligned.m8n8.x4.trans.shared.b16 {%0,%1,%2,%3}, [%4];"
                 : "=r"(r[0]), "=r"(r[1]), "=r"(r[2]), "=r"(r[3]) : "r"(a));
}
__device__ __forceinline__ void mma16816(float* c, const u32* a, u32 b0, u32 b1) {
    asm volatile(
        "mma.sync.aligned.m16n8k16.row.col.f32.f16.f16.f32 "
        "{%0,%1,%2,%3}, {%4,%5,%6,%7}, {%8,%9}, {%0,%1,%2,%3};"
        : "+f"(c[0]), "+f"(c[1]), "+f"(c[2]), "+f"(c[3])
        : "r"(a[0]), "r"(a[1]), "r"(a[2]), "r"(a[3]), "r"(b0), "r"(b1));
}
__device__ __forceinline__ u32 pack_half2(float a, float b) {
    __half2 h = __floats2half2_rn(a, b);
    return *reinterpret_cast<u32*>(&h);
}

// ---------------------------------------------------------------------------
// Attention with fp16 tensor-core matmuls + online softmax.
// One block per (window, head); 608 threads = 19 warps; warp w owns rows
// [16w, 16w+16) of the padded 304-row strip.
// ---------------------------------------------------------------------------
#define SMEM_ATTN_BYTES ((3 * NPAD * QKPAD) * 2 + (NBIAS + NTOK + NTOK) * 4)

__global__ void __launch_bounds__(608)
attn_kernel(const float* __restrict__ qkv, const int* __restrict__ mask,
            const float* __restrict__ bias_table, float* __restrict__ aout) {
    extern __shared__ char smraw[];
    __half* Qh = (__half*)smraw;
    __half* Kh = Qh + NPAD * QKPAD;
    __half* Vh = Kh + NPAD * QKPAD;
    float*  biasC = (float*)(Vh + NPAD * QKPAD);
    float*  msk   = biasC + NBIAS;
    int*    ccode = (int*)(msk + NTOK);

    const int w = blockIdx.x;
    const int h = blockIdx.y;
    const int tid = threadIdx.x;
    const float scale = 0.17677669529663687f;  // 32^-0.5

    // Stage Q/K/V as fp16 (zeros in pad rows 294..303)
    const float* qbase = qkv + (long)w * NTOK * (3 * DIM) + h * DH;
    for (int idx = tid; idx < NPAD * DH; idx += 608) {
        int t = idx >> 5, d = idx & 31;
        __half qv = __float2half(0.f), kv = qv, vv = qv;
        if (t < NTOK) {
            long o = (long)t * (3 * DIM) + d;
            qv = __float2half(qbase[o]);
            kv = __float2half(qbase[o + DIM]);
            vv = __float2half(qbase[o + 2 * DIM]);
        }
        Qh[t * QKPAD + d] = qv;
        Kh[t * QKPAD + d] = kv;
        Vh[t * QKPAD + d] = vv;
    }
    for (int i = tid; i < NBIAS; i += 608) biasC[i] = bias_table[i * HEADS + h];
    const int* mbase = mask + (long)w * NTOK;
    for (int j = tid; j < NTOK; j += 608) {
        int l = j / 49, r = j % 49;
        msk[j] = (float)mbase[r * AGENT + l];
        ccode[j] = l * 169 + (r / 7) * 13 + (r % 7);
    }
    __syncthreads();

    const int warp = tid >> 5, lane = tid & 31;
    const int m0 = warp * 16;
    const int g = lane >> 2, t4 = lane & 3;
    const int row0 = m0 + g, row1 = row0 + 8;
    const int lr = lane & 7, sel = lane >> 3;

    // Q fragments for this strip (k=0..15 and 16..31), held for the whole loop
    u32 qf[8];
    {
        const __half* p0 = Qh + (m0 + lr + (sel & 1) * 8) * QKPAD + (sel >> 1) * 8;
        ldsm4(qf, p0);
        ldsm4(qf + 4, p0 + 16);
    }
    const int rc0 = ccode[row0 < NTOK ? row0 : NTOK - 1] + 929;  // 5*169+6*13+6
    const int rc1 = ccode[row1 < NTOK ? row1 : NTOK - 1] + 929;

    float m_0 = -3.0e38f, m_1 = -3.0e38f, l_0 = 0.f, l_1 = 0.f;
    float O[4][4];
#pragma unroll
    for (int i = 0; i < 4; i++)
#pragma unroll
        for (int j = 0; j < 4; j++) O[i][j] = 0.f;

    for (int j0 = 0; j0 < NPAD; j0 += 16) {
        // K fragments: kf0 = cols 0-15, kf1 = cols 16-31; within each x4:
        // r0/r1 = b0/b1 for tokens j0..j0+7 (n-tile0), r2/r3 for j0+8..15.
        u32 kf0[4], kf1[4];
        {
            const __half* pk = Kh + (j0 + lr + (sel >> 1) * 8) * QKPAD + (sel & 1) * 8;
            ldsm4(kf0, pk);
            ldsm4(kf1, pk + 16);
        }
        float s0[4] = {0.f, 0.f, 0.f, 0.f};   // n-tile0: cols j0+0..7
        float s1[4] = {0.f, 0.f, 0.f, 0.f};   // n-tile1: cols j0+8..15
        mma16816(s0, qf, kf0[0], kf0[1]);
        mma16816(s0, qf + 4, kf1[0], kf1[1]);
        mma16816(s1, qf, kf0[2], kf0[3]);
        mma16816(s1, qf + 4, kf1[2], kf1[3]);

        // bias + mask + pad for the 4 columns this thread owns
        int  c0 = j0 + 2 * t4, c1 = c0 + 1, c2 = c0 + 8, c3 = c0 + 9;
        bool v0 = c0 < NTOK, v1 = c1 < NTOK, v2 = c2 < NTOK, v3 = c3 < NTOK;
        int  cc0 = v0 ? ccode[c0] : 0, cc1 = v1 ? ccode[c1] : 0;
        int  cc2 = v2 ? ccode[c2] : 0, cc3 = v3 ? ccode[c3] : 0;
        float mv0 = v0 ? msk[c0] : 0.f, mv1 = v1 ? msk[c1] : 0.f;
        float mv2 = v2 ? msk[c2] : 0.f, mv3 = v3 ? msk[c3] : 0.f;

        float sv00 = !v0 ? -3.0e38f : (mv0 == 0.f ? -1e9f : fmaf(s0[0], scale, biasC[rc0 - cc0]));
        float sv01 = !v1 ? -3.0e38f : (mv1 == 0.f ? -1e9f : fmaf(s0[1], scale, biasC[rc0 - cc1]));
        float sv02 = !v0 ? -3.0e38f : (mv0 == 0.f ? -1e9f : fmaf(s0[2], scale, biasC[rc1 - cc0]));
        float sv03 = !v1 ? -3.0e38f : (mv1 == 0.f ? -1e9f : fmaf(s0[3], scale, biasC[rc1 - cc1]));
        float sv10 = !v2 ? -3.0e38f : (mv2 == 0.f ? -1e9f : fmaf(s1[0], scale, biasC[rc0 - cc2]));
        float sv11 = !v3 ? -3.0e38f : (mv3 == 0.f ? -1e9f : fmaf(s1[1], scale, biasC[rc0 - cc3]));
        float sv12 = !v2 ? -3.0e38f : (mv2 == 0.f ? -1e9f : fmaf(s1[2], scale, biasC[rc1 - cc2]));
        float sv13 = !v3 ? -3.0e38f : (mv3 == 0.f ? -1e9f : fmaf(s1[3], scale, biasC[rc1 - cc3]));

        // online softmax (rows row0 and row1)
        float rmax0 = fmaxf(fmaxf(sv00, sv01), fmaxf(sv10, sv11));
        float rmax1 = fmaxf(fmaxf(sv02, sv03), fmaxf(sv12, sv13));
        rmax0 = fmaxf(rmax0, __shfl_xor_sync(0xffffffffu, rmax0, 1));
        rmax0 = fmaxf(rmax0, __shfl_xor_sync(0xffffffffu, rmax0, 2));
        rmax1 = fmaxf(rmax1, __shfl_xor_sync(0xffffffffu, rmax1, 1));
        rmax1 = fmaxf(rmax1, __shfl_xor_sync(0xffffffffu, rmax1, 2));
        float mn0 = fmaxf(m_0, rmax0), mn1 = fmaxf(m_1, rmax1);
        float f0 = __expf(m_0 - mn0), f1 = __expf(m_1 - mn1);
        m_0 = mn0; m_1 = mn1;

        float p00 = __expf(sv00 - mn0), p01 = __expf(sv01 - mn0);
        float p02 = __expf(sv02 - mn1), p03 = __expf(sv03 - mn1);
        float p10 = __expf(sv10 - mn0), p11 = __expf(sv11 - mn0);
        float p12 = __expf(sv12 - mn1), p13 = __expf(sv13 - mn1);

        float rs0 = p00 + p01 + p10 + p11;
        float rs1 = p02 + p03 + p12 + p13;
        rs0 += __shfl_xor_sync(0xffffffffu, rs0, 1);
        rs0 += __shfl_xor_sync(0xffffffffu, rs0, 2);
        rs1 += __shfl_xor_sync(0xffffffffu, rs1, 1);
        rs1 += __shfl_xor_sync(0xffffffffu, rs1, 2);
        l_0 = l_0 * f0 + rs0;
        l_1 = l_1 * f1 + rs1;

#pragma unroll
        for (int dt = 0; dt < 4; dt++) {
            O[dt][0] *= f0; O[dt][1] *= f0;
            O[dt][2] *= f1; O[dt][3] *= f1;
        }

        // pack P into AV A-fragment (rows row0/row1, k-local 0..15)
        u32 pa[4];
        pa[0] = pack_half2(p00, p01);
        pa[1] = pack_half2(p02, p03);
        pa[2] = pack_half2(p10, p11);
        pa[3] = pack_half2(p12, p13);

        // V fragments: vf0 = d-tiles 0,1 ; vf1 = d-tiles 2,3
        u32 vf0[4], vf1[4];
        {
            const __half* pv = Vh + (j0 + lr + (sel & 1) * 8) * QKPAD + (sel >> 1) * 8;
            ldsm4t(vf0, pv);
            ldsm4t(vf1, pv + 16);
        }
        mma16816(O[0], pa, vf0[0], vf0[1]);
        mma16816(O[1], pa, vf0[2], vf0[3]);
        mma16816(O[2], pa, vf1[0], vf1[1]);
        mma16816(O[3], pa, vf1[2], vf1[3]);
    }

    float inv0 = 1.f / l_0, inv1 = 1.f / l_1;
#pragma unroll
    for (int dt = 0; dt < 4; dt++) {
        int d0 = dt * 8 + 2 * t4;
        if (row0 < NTOK) {
            long base = ((long)w * NTOK + row0) * DIM + h * DH + d0;
            aout[base]     = O[dt][0] * inv0;
            aout[base + 1] = O[dt][1] * inv0;
        }
        if (row1 < NTOK) {
            long base = ((long)w * NTOK + row1) * DIM + h * DH + d0;
            aout[base]     = O[dt][2] * inv1;
            aout[base + 1] = O[dt][3] * inv1;
        }
    }
}

// ---------------------------------------------------------------------------
extern "C" void kernel_launch(void* const* d_in, const int* in_sizes, int n_in,
                              void* d_out, int out_size) {
    const float* x          = (const float*)d_in[0];
    const int*   mask       = (const int*)d_in[1];
    const float* w_qkv      = (const float*)d_in[2];
    const float* w_out      = (const float*)d_in[3];
    const float* bias_table = (const float*)d_in[4];
    float* out = (float*)d_out;

    void *rbp_, *qkvp_, *attp_;
    cudaGetSymbolAddress(&rbp_, g_rowbase);
    cudaGetSymbolAddress(&qkvp_, g_qkv);
    cudaGetSymbolAddress(&attp_, g_att);
    int*   rb   = (int*)rbp_;
    float* qkvb = (float*)qkvp_;
    float* attb = (float*)attp_;

    cudaFuncSetAttribute(attn_kernel, cudaFuncAttributeMaxDynamicSharedMemorySize,
                         SMEM_ATTN_BYTES);

    rowbase_kernel<<<(MROWS + 255) / 256, 256>>>(rb);

    // QKV projection: (37632 x 256) @ (768 x 256)^T -> (37632 x 768)
    {
        dim3 grid(3 * DIM / 128, MROWS / 128);
        gemm_kernel<1, 0><<<grid, 256>>>(x, rb, w_qkv, qkvb, 3 * DIM);
    }

    // Attention per (window, head)
    {
        dim3 grid(NWIN, HEADS);
        attn_kernel<<<grid, 608, SMEM_ATTN_BYTES>>>(qkvb, mask, bias_table, attb);
    }

    // Output projection + scatter to (B, L, X, Y, W1, W2, C)
    {
        dim3 grid(DIM / 128, MROWS / 128);
        gemm_kernel<0, 1><<<grid, 256>>>(attb, rb, w_out, out, DIM);
    }
}

// round 17
// speedup vs baseline: 3.3411x; 1.6278x over previous
#include <cuda_runtime.h>
#include <cuda_fp16.h>
#include <cuda_bf16.h>
#include <cstdint>
#include <cstring>

typedef unsigned int u32;

// Problem constants
#define BATCH   2
#define AGENT   6
#define XW      8
#define YW      8
#define WIN     7
#define DIM     256
#define HEADS   8
#define DH      32
#define NWIN    (BATCH * XW * YW)      // 128 windows
#define NTOK    (AGENT * WIN * WIN)    // 294 tokens per window
#define MROWS   (NWIN * NTOK)          // 37632
#define NBIAS   1859                   // (2*6-1)*13*13

#define NPAD    304                    // NTOK padded to 19*16
#define QKPAD   40                     // halves per row (80 B: conflict-free ldmatrix)

__device__ int    g_rowbase[MROWS];
__device__ __half g_xh[(size_t)MROWS * DIM];        // 19.3 MB (x as fp16, same layout)
__device__ __half g_wqkvh[3 * DIM * DIM];           // 768x256
__device__ __half g_wouth[DIM * DIM];               // 256x256
__device__ __half g_qkvh[(size_t)MROWS * 3 * DIM];  // 57.8 MB
__device__ __half g_atth[(size_t)MROWS * DIM];      // 19.3 MB

// ---------------------------------------------------------------------------
__global__ void rowbase_kernel(int* __restrict__ rb) {
    int m = blockIdx.x * 256 + threadIdx.x;
    if (m >= MROWS) return;
    int w = m / NTOK, t = m % NTOK;
    int b = w >> 6, xy = w & 63, x_ = xy >> 3, y_ = xy & 7;
    int l = t / 49, r = t % 49, w1 = r / 7, w2 = r % 7;
    rb[m] = ((((((b * AGENT + l) * XW + x_) * YW + y_) * WIN + w1) * WIN + w2)) * DIM;
}

__global__ void f2h_kernel(const float* __restrict__ src, __half* __restrict__ dst, int n) {
    int i = blockIdx.x * 256 + threadIdx.x;
    if (i < n) dst[i] = __float2half(src[i]);
}

// ---------------------------------------------------------------------------
// mma.sync helpers
// ---------------------------------------------------------------------------
__device__ __forceinline__ void ldsm4(u32* r, const __half* p) {
    u32 a = (u32)__cvta_generic_to_shared(p);
    asm volatile("ldmatrix.sync.aligned.m8n8.x4.shared.b16 {%0,%1,%2,%3}, [%4];"
                 : "=r"(r[0]), "=r"(r[1]), "=r"(r[2]), "=r"(r[3]) : "r"(a));
}
__device__ __forceinline__ void ldsm4t(u32* r, const __half* p) {
    u32 a = (u32)__cvta_generic_to_shared(p);
    asm volatile("ldmatrix.sync.aligned.m8n8.x4.trans.shared.b16 {%0,%1,%2,%3}, [%4];"
                 : "=r"(r[0]), "=r"(r[1]), "=r"(r[2]), "=r"(r[3]) : "r"(a));
}
__device__ __forceinline__ void mma16816(float* c, const u32* a, u32 b0, u32 b1) {
    asm volatile(
        "mma.sync.aligned.m16n8k16.row.col.f32.f16.f16.f32 "
        "{%0,%1,%2,%3}, {%4,%5,%6,%7}, {%8,%9}, {%0,%1,%2,%3};"
        : "+f"(c[0]), "+f"(c[1]), "+f"(c[2]), "+f"(c[3])
        : "r"(a[0]), "r"(a[1]), "r"(a[2]), "r"(a[3]), "r"(b0), "r"(b1));
}
__device__ __forceinline__ u32 pack_half2(float a, float b) {
    __half2 h = __floats2half2_rn(a, b);
    return *reinterpret_cast<u32*>(&h);
}

// ---------------------------------------------------------------------------
// fp16 HMMA GEMM: C[m][n] = sum_k A[m][k] * W[n][k], K = 256.
// BM=128, BN=64, BK=32; 256 threads = 8 warps, each warp one m16 strip x BN.
// MODE 0: A gathered via rowbase (x), fp16 out contiguous (N=768).
// MODE 1: A contiguous (att out), fp32 out scattered via rowbase (N=256).
// ---------------------------------------------------------------------------
template <int MODE>
__global__ void __launch_bounds__(256)
gemm16_kernel(const __half* __restrict__ A, const int* __restrict__ rowbase,
              const __half* __restrict__ W, __half* __restrict__ Ch,
              float* __restrict__ Cf, int N) {
    __shared__ __half Ash[128 * QKPAD];
    __shared__ __half Bsh[64 * QKPAD];

    const int tid = threadIdx.x;
    const int bm = blockIdx.y * 128;
    const int bn = blockIdx.x * 64;

    const int warp = tid >> 5, lane = tid & 31;
    const int g = lane >> 2, t4 = lane & 3;
    const int lr = lane & 7, sel = lane >> 3;
    const int m0 = warp * 16;

    float acc[4][2][4];
#pragma unroll
    for (int i = 0; i < 4; i++)
#pragma unroll
        for (int j = 0; j < 2; j++)
#pragma unroll
            for (int k = 0; k < 4; k++) acc[i][j][k] = 0.f;

    for (int k0 = 0; k0 < DIM; k0 += 32) {
        // Load A tile: 128 rows x 32 halves = 512 int4 segments (2/thread)
#pragma unroll
        for (int t = 0; t < 2; t++) {
            int i = tid + t * 256;          // 0..511
            int row = i >> 2, seg = i & 3;
            long ab = MODE == 0 ? (long)rowbase[bm + row] : (long)(bm + row) * DIM;
            *(int4*)(Ash + row * QKPAD + seg * 8) =
                *(const int4*)(A + ab + k0 + seg * 8);
        }
        // Load B tile: 64 rows x 32 halves = 256 int4 segments (1/thread)
        {
            int row = tid >> 2, seg = tid & 3;
            *(int4*)(Bsh + row * QKPAD + seg * 8) =
                *(const int4*)(W + (long)(bn + row) * DIM + k0 + seg * 8);
        }
        __syncthreads();

        // A fragment: m16 x k32
        u32 af[8];
        {
            const __half* pa = Ash + (m0 + lr + (sel & 1) * 8) * QKPAD + (sel >> 1) * 8;
            ldsm4(af, pa);
            ldsm4(af + 4, pa + 16);
        }
        // B fragments: 4 n16-groups
#pragma unroll
        for (int gn = 0; gn < 4; gn++) {
            u32 bf0[4], bf1[4];
            const __half* pb = Bsh + (gn * 16 + lr + (sel >> 1) * 8) * QKPAD + (sel & 1) * 8;
            ldsm4(bf0, pb);
            ldsm4(bf1, pb + 16);
            mma16816(acc[gn][0], af, bf0[0], bf0[1]);
            mma16816(acc[gn][0], af + 4, bf1[0], bf1[1]);
            mma16816(acc[gn][1], af, bf0[2], bf0[3]);
            mma16816(acc[gn][1], af + 4, bf1[2], bf1[3]);
        }
        __syncthreads();
    }

    // Write out
    const int row0 = bm + m0 + g, row1 = row0 + 8;
#pragma unroll
    for (int gn = 0; gn < 4; gn++) {
#pragma unroll
        for (int tile = 0; tile < 2; tile++) {
            int col = bn + gn * 16 + tile * 8 + 2 * t4;
            if (MODE == 0) {
                *(u32*)(Ch + (long)row0 * N + col) = pack_half2(acc[gn][tile][0], acc[gn][tile][1]);
                *(u32*)(Ch + (long)row1 * N + col) = pack_half2(acc[gn][tile][2], acc[gn][tile][3]);
            } else {
                float* p0 = Cf + (long)rowbase[row0] + col;
                float* p1 = Cf + (long)rowbase[row1] + col;
                *(float2*)p0 = make_float2(acc[gn][tile][0], acc[gn][tile][1]);
                *(float2*)p1 = make_float2(acc[gn][tile][2], acc[gn][tile][3]);
            }
        }
    }
}

// ---------------------------------------------------------------------------
// Attention with fp16 tensor-core matmuls + online softmax.
// One block per (window, head); 608 threads = 19 warps; warp w owns rows
// [16w, 16w+16). Reads fp16 qkv, writes fp16 attention output.
// ---------------------------------------------------------------------------
#define SMEM_ATTN_BYTES ((3 * NPAD * QKPAD) * 2 + (NBIAS + NTOK + NTOK) * 4)

__global__ void __launch_bounds__(608)
attn_kernel(const __half* __restrict__ qkv, const int* __restrict__ mask,
            const float* __restrict__ bias_table, __half* __restrict__ aout) {
    extern __shared__ char smraw[];
    __half* Qh = (__half*)smraw;
    __half* Kh = Qh + NPAD * QKPAD;
    __half* Vh = Kh + NPAD * QKPAD;
    float*  biasC = (float*)(Vh + NPAD * QKPAD);
    float*  msk   = biasC + NBIAS;
    int*    ccode = (int*)(msk + NTOK);

    const int w = blockIdx.x;
    const int h = blockIdx.y;
    const int tid = threadIdx.x;
    const float scale = 0.17677669529663687f;  // 32^-0.5

    // Stage Q/K/V (already fp16; zeros in pad rows 294..303)
    const __half* qbase = qkv + (long)w * NTOK * (3 * DIM) + h * DH;
    const __half zero = __float2half(0.f);
    for (int idx = tid; idx < NPAD * DH; idx += 608) {
        int t = idx >> 5, d = idx & 31;
        __half qv = zero, kv = zero, vv = zero;
        if (t < NTOK) {
            long o = (long)t * (3 * DIM) + d;
            qv = qbase[o];
            kv = qbase[o + DIM];
            vv = qbase[o + 2 * DIM];
        }
        Qh[t * QKPAD + d] = qv;
        Kh[t * QKPAD + d] = kv;
        Vh[t * QKPAD + d] = vv;
    }
    for (int i = tid; i < NBIAS; i += 608) biasC[i] = bias_table[i * HEADS + h];
    const int* mbase = mask + (long)w * NTOK;
    for (int j = tid; j < NTOK; j += 608) {
        int l = j / 49, r = j % 49;
        msk[j] = (float)mbase[r * AGENT + l];
        ccode[j] = l * 169 + (r / 7) * 13 + (r % 7);
    }
    __syncthreads();

    const int warp = tid >> 5, lane = tid & 31;
    const int m0 = warp * 16;
    const int g = lane >> 2, t4 = lane & 3;
    const int row0 = m0 + g, row1 = row0 + 8;
    const int lr = lane & 7, sel = lane >> 3;

    u32 qf[8];
    {
        const __half* p0 = Qh + (m0 + lr + (sel & 1) * 8) * QKPAD + (sel >> 1) * 8;
        ldsm4(qf, p0);
        ldsm4(qf + 4, p0 + 16);
    }
    const int rc0 = ccode[row0 < NTOK ? row0 : NTOK - 1] + 929;  // 5*169+6*13+6
    const int rc1 = ccode[row1 < NTOK ? row1 : NTOK - 1] + 929;

    float m_0 = -3.0e38f, m_1 = -3.0e38f, l_0 = 0.f, l_1 = 0.f;
    float O[4][4];
#pragma unroll
    for (int i = 0; i < 4; i++)
#pragma unroll
        for (int j = 0; j < 4; j++) O[i][j] = 0.f;

    for (int j0 = 0; j0 < NPAD; j0 += 16) {
        u32 kf0[4], kf1[4];
        {
            const __half* pk = Kh + (j0 + lr + (sel >> 1) * 8) * QKPAD + (sel & 1) * 8;
            ldsm4(kf0, pk);
            ldsm4(kf1, pk + 16);
        }
        float s0[4] = {0.f, 0.f, 0.f, 0.f};
        float s1[4] = {0.f, 0.f, 0.f, 0.f};
        mma16816(s0, qf, kf0[0], kf0[1]);
        mma16816(s0, qf + 4, kf1[0], kf1[1]);
        mma16816(s1, qf, kf0[2], kf0[3]);
        mma16816(s1, qf + 4, kf1[2], kf1[3]);

        int  c0 = j0 + 2 * t4, c1 = c0 + 1, c2 = c0 + 8, c3 = c0 + 9;
        bool v0 = c0 < NTOK, v1 = c1 < NTOK, v2 = c2 < NTOK, v3 = c3 < NTOK;
        int  cc0 = v0 ? ccode[c0] : 0, cc1 = v1 ? ccode[c1] : 0;
        int  cc2 = v2 ? ccode[c2] : 0, cc3 = v3 ? ccode[c3] : 0;
        float mv0 = v0 ? msk[c0] : 0.f, mv1 = v1 ? msk[c1] : 0.f;
        float mv2 = v2 ? msk[c2] : 0.f, mv3 = v3 ? msk[c3] : 0.f;

        float sv00 = !v0 ? -3.0e38f : (mv0 == 0.f ? -1e9f : fmaf(s0[0], scale, biasC[rc0 - cc0]));
        float sv01 = !v1 ? -3.0e38f : (mv1 == 0.f ? -1e9f : fmaf(s0[1], scale, biasC[rc0 - cc1]));
        float sv02 = !v0 ? -3.0e38f : (mv0 == 0.f ? -1e9f : fmaf(s0[2], scale, biasC[rc1 - cc0]));
        float sv03 = !v1 ? -3.0e38f : (mv1 == 0.f ? -1e9f : fmaf(s0[3], scale, biasC[rc1 - cc1]));
        float sv10 = !v2 ? -3.0e38f : (mv2 == 0.f ? -1e9f : fmaf(s1[0], scale, biasC[rc0 - cc2]));
        float sv11 = !v3 ? -3.0e38f : (mv3 == 0.f ? -1e9f : fmaf(s1[1], scale, biasC[rc0 - cc3]));
        float sv12 = !v2 ? -3.0e38f : (mv2 == 0.f ? -1e9f : fmaf(s1[2], scale, biasC[rc1 - cc2]));
        float sv13 = !v3 ? -3.0e38f : (mv3 == 0.f ? -1e9f : fmaf(s1[3], scale, biasC[rc1 - cc3]));

        float rmax0 = fmaxf(fmaxf(sv00, sv01), fmaxf(sv10, sv11));
        float rmax1 = fmaxf(fmaxf(sv02, sv03), fmaxf(sv12, sv13));
        rmax0 = fmaxf(rmax0, __shfl_xor_sync(0xffffffffu, rmax0, 1));
        rmax0 = fmaxf(rmax0, __shfl_xor_sync(0xffffffffu, rmax0, 2));
        rmax1 = fmaxf(rmax1, __shfl_xor_sync(0xffffffffu, rmax1, 1));
        rmax1 = fmaxf(rmax1, __shfl_xor_sync(0xffffffffu, rmax1, 2));
        float mn0 = fmaxf(m_0, rmax0), mn1 = fmaxf(m_1, rmax1);
        float f0 = __expf(m_0 - mn0), f1 = __expf(m_1 - mn1);
        m_0 = mn0; m_1 = mn1;

        float p00 = __expf(sv00 - mn0), p01 = __expf(sv01 - mn0);
        float p02 = __expf(sv02 - mn1), p03 = __expf(sv03 - mn1);
        float p10 = __expf(sv10 - mn0), p11 = __expf(sv11 - mn0);
        float p12 = __expf(sv12 - mn1), p13 = __expf(sv13 - mn1);

        float rs0 = p00 + p01 + p10 + p11;
        float rs1 = p02 + p03 + p12 + p13;
        rs0 += __shfl_xor_sync(0xffffffffu, rs0, 1);
        rs0 += __shfl_xor_sync(0xffffffffu, rs0, 2);
        rs1 += __shfl_xor_sync(0xffffffffu, rs1, 1);
        rs1 += __shfl_xor_sync(0xffffffffu, rs1, 2);
        l_0 = l_0 * f0 + rs0;
        l_1 = l_1 * f1 + rs1;

#pragma unroll
        for (int dt = 0; dt < 4; dt++) {
            O[dt][0] *= f0; O[dt][1] *= f0;
            O[dt][2] *= f1; O[dt][3] *= f1;
        }

        u32 pa[4];
        pa[0] = pack_half2(p00, p01);
        pa[1] = pack_half2(p02, p03);
        pa[2] = pack_half2(p10, p11);
        pa[3] = pack_half2(p12, p13);

        u32 vf0[4], vf1[4];
        {
            const __half* pv = Vh + (j0 + lr + (sel & 1) * 8) * QKPAD + (sel >> 1) * 8;
            ldsm4t(vf0, pv);
            ldsm4t(vf1, pv + 16);
        }
        mma16816(O[0], pa, vf0[0], vf0[1]);
        mma16816(O[1], pa, vf0[2], vf0[3]);
        mma16816(O[2], pa, vf1[0], vf1[1]);
        mma16816(O[3], pa, vf1[2], vf1[3]);
    }

    float inv0 = 1.f / l_0, inv1 = 1.f / l_1;
#pragma unroll
    for (int dt = 0; dt < 4; dt++) {
        int d0 = dt * 8 + 2 * t4;
        if (row0 < NTOK) {
            long base = ((long)w * NTOK + row0) * DIM + h * DH + d0;
            *(u32*)(aout + base) = pack_half2(O[dt][0] * inv0, O[dt][1] * inv0);
        }
        if (row1 < NTOK) {
            long base = ((long)w * NTOK + row1) * DIM + h * DH + d0;
            *(u32*)(aout + base) = pack_half2(O[dt][2] * inv1, O[dt][3] * inv1);
        }
    }
}

// ---------------------------------------------------------------------------
extern "C" void kernel_launch(void* const* d_in, const int* in_sizes, int n_in,
                              void* d_out, int out_size) {
    const float* x          = (const float*)d_in[0];
    const int*   mask       = (const int*)d_in[1];
    const float* w_qkv      = (const float*)d_in[2];
    const float* w_out      = (const float*)d_in[3];
    const float* bias_table = (const float*)d_in[4];
    float* out = (float*)d_out;

    void *rbp_, *xhp_, *wqp_, *wop_, *qkvp_, *attp_;
    cudaGetSymbolAddress(&rbp_, g_rowbase);
    cudaGetSymbolAddress(&xhp_, g_xh);
    cudaGetSymbolAddress(&wqp_, g_wqkvh);
    cudaGetSymbolAddress(&wop_, g_wouth);
    cudaGetSymbolAddress(&qkvp_, g_qkvh);
    cudaGetSymbolAddress(&attp_, g_atth);
    int*    rb    = (int*)rbp_;
    __half* xh    = (__half*)xhp_;
    __half* wqh   = (__half*)wqp_;
    __half* woh   = (__half*)wop_;
    __half* qkvh  = (__half*)qkvp_;
    __half* atth  = (__half*)attp_;

    cudaFuncSetAttribute(attn_kernel, cudaFuncAttributeMaxDynamicSharedMemorySize,
                         SMEM_ATTN_BYTES);

    rowbase_kernel<<<(MROWS + 255) / 256, 256>>>(rb);

    // fp32 -> fp16 conversions
    f2h_kernel<<<(MROWS * DIM + 255) / 256, 256>>>(x, xh, MROWS * DIM);
    f2h_kernel<<<(3 * DIM * DIM + 255) / 256, 256>>>(w_qkv, wqh, 3 * DIM * DIM);
    f2h_kernel<<<(DIM * DIM + 255) / 256, 256>>>(w_out, woh, DIM * DIM);

    // QKV projection (HMMA): gathered A, fp16 out, N=768
    {
        dim3 grid(3 * DIM / 64, MROWS / 128);
        gemm16_kernel<0><<<grid, 256>>>(xh, rb, wqh, qkvh, nullptr, 3 * DIM);
    }

    // Attention per (window, head)
    {
        dim3 grid(NWIN, HEADS);
        attn_kernel<<<grid, 608, SMEM_ATTN_BYTES>>>(qkvh, mask, bias_table, atth);
    }

    // Output projection (HMMA): contiguous A, fp32 scattered out, N=256
    {
        dim3 grid(DIM / 64, MROWS / 128);
        gemm16_kernel<1><<<grid, 256>>>(atth, rb, woh, nullptr, out, DIM);
    }
}